// round 1
// baseline (speedup 1.0000x reference)
#include <cuda_runtime.h>
#include <cstdint>

// Problem constants (fixed shapes per reference)
#define NN 50000
#define EE 800000
#define IN_F 128
#define KTOP 32

// Scratch (static device globals: allocation-free)
__device__ int   g_deg[NN];
__device__ float g_winv[NN];
__device__ float g_agg[(size_t)NN * IN_F];   // 25.6 MB

// ---------------------------------------------------------------------------
// Kernel 1: zero agg + deg
// ---------------------------------------------------------------------------
__global__ void k_zero() {
    size_t i = (size_t)blockIdx.x * blockDim.x + threadIdx.x;
    size_t stride = (size_t)gridDim.x * blockDim.x;
    const size_t total4 = (size_t)NN * IN_F / 4;
    float4 z = make_float4(0.f, 0.f, 0.f, 0.f);
    for (size_t j = i; j < total4; j += stride)
        reinterpret_cast<float4*>(g_agg)[j] = z;
    for (size_t j = i; j < NN; j += stride)
        g_deg[j] = 0;
}

// ---------------------------------------------------------------------------
// Kernel 2: in-degree histogram over dst
// ---------------------------------------------------------------------------
__global__ void k_deg(const int* __restrict__ dst) {
    int i = blockIdx.x * blockDim.x + threadIdx.x;
    if (i < EE) atomicAdd(&g_deg[dst[i]], 1);
}

// ---------------------------------------------------------------------------
// Kernel 3: winv = 1 / max(deg, 1)
// ---------------------------------------------------------------------------
__global__ void k_winv() {
    int i = blockIdx.x * blockDim.x + threadIdx.x;
    if (i < NN) g_winv[i] = 1.0f / fmaxf((float)g_deg[i], 1.0f);
}

// ---------------------------------------------------------------------------
// Kernel 4: edge scatter. One warp per edge; lane k handles top-k entry k.
// Duplicate indices within a row: reference .set() semantics = last write
// wins -> keep only the HIGHEST k among equal indices (match_any + msb).
// ---------------------------------------------------------------------------
__global__ void k_scatter(const float* __restrict__ topk_values,
                          const int*   __restrict__ topk_indices,
                          const int*   __restrict__ src,
                          const int*   __restrict__ dst) {
    int tid  = blockIdx.x * blockDim.x + threadIdx.x;
    int e    = tid >> 5;
    int lane = tid & 31;
    if (e >= EE) return;

    int s = src[e];            // broadcast within warp
    int d = dst[e];
    float v  = topk_values[(size_t)s * KTOP + lane];
    int   ix = topk_indices[(size_t)s * KTOP + lane];

    unsigned peers = __match_any_sync(0xffffffffu, ix);
    bool keep = (lane == (31 - __clz(peers)));   // highest lane in dup group

    float w = g_winv[d];
    if (keep) atomicAdd(&g_agg[(size_t)d * IN_F + ix], w * v);
}

// ---------------------------------------------------------------------------
// Kernel 5: fused GEMM  out = [feat | agg] @ [W_self ; W_neigh] + b_self
// M = NN, N = 128, K = 256.  128x128 tile, BK=16, 8x8 per thread, 256 thr.
// ---------------------------------------------------------------------------
#define BM 128
#define BN 128
#define BK 16

__global__ __launch_bounds__(256, 2)
void k_gemm(const float* __restrict__ feat,
            const float* __restrict__ Wself,
            const float* __restrict__ bself,
            const float* __restrict__ Wneigh,
            float* __restrict__ out) {
    __shared__ float As[BK][BM + 4];
    __shared__ float Bs[BK][BN];

    const int t  = threadIdx.x;
    const int m0 = blockIdx.x * BM;
    const int tx = t & 15;     // 0..15 -> output cols tx*8..
    const int ty = t >> 4;     // 0..15 -> output rows ty*8..

    float acc[8][8];
    #pragma unroll
    for (int i = 0; i < 8; i++)
        #pragma unroll
        for (int j = 0; j < 8; j++) acc[i][j] = 0.f;

    for (int kc = 0; kc < 256; kc += BK) {
        const float* Asrc = (kc < 128) ? feat   : g_agg;
        const float* Bsrc = (kc < 128) ? Wself  : Wneigh;
        const int kbase = kc & 127;

        // Load A tile: 128 rows x 16 k = 512 float4, 2 per thread; store
        // transposed As[k][m] so compute reads are contiguous over m.
        #pragma unroll
        for (int l = 0; l < 2; l++) {
            int f4  = t + l * 256;
            int row = f4 >> 2;     // 0..127
            int kq  = f4 & 3;      // 0..3 (k quarter)
            int gr  = m0 + row;
            float4 v = make_float4(0.f, 0.f, 0.f, 0.f);
            if (gr < NN)
                v = *reinterpret_cast<const float4*>(
                        Asrc + (size_t)gr * IN_F + kbase + kq * 4);
            As[kq * 4 + 0][row] = v.x;
            As[kq * 4 + 1][row] = v.y;
            As[kq * 4 + 2][row] = v.z;
            As[kq * 4 + 3][row] = v.w;
        }

        // Load B tile: 16 k x 128 n = 512 float4, 2 per thread.
        #pragma unroll
        for (int l = 0; l < 2; l++) {
            int f4 = t + l * 256;
            int kr = f4 >> 5;      // 0..15
            int nq = f4 & 31;      // 0..31
            float4 v = *reinterpret_cast<const float4*>(
                           Bsrc + (size_t)(kbase + kr) * 128 + nq * 4);
            *reinterpret_cast<float4*>(&Bs[kr][nq * 4]) = v;
        }
        __syncthreads();

        #pragma unroll
        for (int kk = 0; kk < BK; kk++) {
            float a[8], b[8];
            #pragma unroll
            for (int i = 0; i < 8; i++) a[i] = As[kk][ty * 8 + i];
            #pragma unroll
            for (int j = 0; j < 8; j++) b[j] = Bs[kk][tx * 8 + j];
            #pragma unroll
            for (int i = 0; i < 8; i++)
                #pragma unroll
                for (int j = 0; j < 8; j++)
                    acc[i][j] = fmaf(a[i], b[j], acc[i][j]);
        }
        __syncthreads();
    }

    // Epilogue: add bias, store
    #pragma unroll
    for (int i = 0; i < 8; i++) {
        int gr = m0 + ty * 8 + i;
        if (gr < NN) {
            #pragma unroll
            for (int j = 0; j < 8; j += 4) {
                int c = tx * 8 + j;
                float4 v;
                v.x = acc[i][j + 0] + bself[c + 0];
                v.y = acc[i][j + 1] + bself[c + 1];
                v.z = acc[i][j + 2] + bself[c + 2];
                v.w = acc[i][j + 3] + bself[c + 3];
                *reinterpret_cast<float4*>(out + (size_t)gr * IN_F + c) = v;
            }
        }
    }
}

// ---------------------------------------------------------------------------
// Launch
// inputs: feat, topk_values, topk_indices, src, dst, W_self, b_self, W_neigh
// ---------------------------------------------------------------------------
extern "C" void kernel_launch(void* const* d_in, const int* in_sizes, int n_in,
                              void* d_out, int out_size) {
    const float* feat   = (const float*)d_in[0];
    const float* tkv    = (const float*)d_in[1];
    const int*   tki    = (const int*)  d_in[2];
    const int*   src    = (const int*)  d_in[3];
    const int*   dst    = (const int*)  d_in[4];
    const float* Wself  = (const float*)d_in[5];
    const float* bself  = (const float*)d_in[6];
    const float* Wneigh = (const float*)d_in[7];
    float* out = (float*)d_out;

    k_zero<<<2048, 256>>>();
    k_deg<<<(EE + 255) / 256, 256>>>(dst);
    k_winv<<<(NN + 255) / 256, 256>>>();
    k_scatter<<<(EE * 32) / 256, 256>>>(tkv, tki, src, dst);
    k_gemm<<<(NN + BM - 1) / BM, 256>>>(feat, Wself, bself, Wneigh, out);
}